// round 16
// baseline (speedup 1.0000x reference)
#include <cuda_runtime.h>
#include <cuda_bf16.h>
#include <cuda_fp16.h>

#define NN 50000
#define NG 1000
#define HID 64
#define NE_MAX 1600000
#define KW 2048
#define KPAD 72
#define NB 49

typedef unsigned long long u64;
typedef unsigned int u32;

// ---------------- scratch ----------------------------------------------------
__device__ __half g_t[NN * HID];
__device__ __half g_hs[NN * HID];
__device__ __half g_z[NN * HID];
__device__ int g_deg_in[NN];
__device__ int g_deg_out[NN];
__device__ int g_off[NN + 1];
__device__ int g_offtmp[NN];
__device__ int g_ctr[NN];
__device__ int g_bsum[NB];
__device__ int g_bpre[NB];
__device__ int g_csr[NE_MAX];
__device__ float g_norm_src[NN];
__device__ float g_norm_dst[NN];
__device__ __half g_W0h[HID * KW];
__device__ __half g_Bb[1024 * HID];
__device__ __half g_Bg[1024 * HID];

// ---------------- helpers -----------------------------------------------------
__device__ __forceinline__ u32 smem_u32(const void* p) {
    u32 a;
    asm("{ .reg .u64 t; cvta.to.shared.u64 t, %1; cvt.u32.u64 %0, t; }" : "=r"(a) : "l"(p));
    return a;
}
__device__ __forceinline__ void mma_f16(float* d, u32 a0, u32 a1, u32 a2, u32 a3,
                                        u32 b0, u32 b1) {
    asm volatile(
        "mma.sync.aligned.m16n8k16.row.col.f32.f16.f16.f32 "
        "{%0,%1,%2,%3}, {%4,%5,%6,%7}, {%8,%9}, {%0,%1,%2,%3};"
        : "+f"(d[0]), "+f"(d[1]), "+f"(d[2]), "+f"(d[3])
        : "r"(a0), "r"(a1), "r"(a2), "r"(a3), "r"(b0), "r"(b1));
}
__device__ __forceinline__ void cp16(u32 daddr, const void* gp, int zf) {
    asm volatile("cp.async.ca.shared.global [%0], [%1], 16, %2;"
                 :: "r"(daddr), "l"(gp), "r"(zf));
}
__device__ __forceinline__ void cp16f(u32 daddr, const void* gp) {
    asm volatile("cp.async.ca.shared.global [%0], [%1], 16;"
                 :: "r"(daddr), "l"(gp));
}
__device__ __forceinline__ void acc8(float* acc, uint4 raw, float w) {
    float2 p0 = __half22float2(*(__half2*)&raw.x);
    float2 p1 = __half22float2(*(__half2*)&raw.y);
    float2 p2 = __half22float2(*(__half2*)&raw.z);
    float2 p3 = __half22float2(*(__half2*)&raw.w);
    acc[0] = fmaf(p0.x, w, acc[0]); acc[1] = fmaf(p0.y, w, acc[1]);
    acc[2] = fmaf(p1.x, w, acc[2]); acc[3] = fmaf(p1.y, w, acc[3]);
    acc[4] = fmaf(p2.x, w, acc[4]); acc[5] = fmaf(p2.y, w, acc[5]);
    acc[6] = fmaf(p3.x, w, acc[6]); acc[7] = fmaf(p3.y, w, acc[7]);
}

// ---------------- weight pre-conversion ---------------------------------------
__global__ void k_prep(const float* __restrict__ W0, const float* __restrict__ W1) {
    int idx = blockIdx.x * blockDim.x + threadIdx.x;
    if (idx < HID * KW) {
        int n = idx / KW, k = idx % KW;
        float w = (k < 2 * NG) ? W0[k * HID + n] : 0.f;
        g_W0h[idx] = __float2half(w);
    }
    if (idx < 1024 * HID) {
        int g = idx / HID, k = idx % HID;
        float wb = (g < NG) ? W1[k * 2 * NG + g] : 0.f;
        float wg = (g < NG) ? W1[k * 2 * NG + NG + g] : 0.f;
        g_Bb[idx] = __float2half(wb);
        g_Bg[idx] = __float2half(wg);
    }
}

// ---------------- degree count -------------------------------------------------
__global__ void k_count(const int* __restrict__ src, const int* __restrict__ dst, int E) {
    int e4 = (blockIdx.x * blockDim.x + threadIdx.x) * 4;
    if (e4 + 3 < E) {
        int4 s = *(const int4*)&src[e4];
        int4 d = *(const int4*)&dst[e4];
        atomicAdd(&g_deg_out[s.x], 1); atomicAdd(&g_deg_out[s.y], 1);
        atomicAdd(&g_deg_out[s.z], 1); atomicAdd(&g_deg_out[s.w], 1);
        atomicAdd(&g_deg_in[d.x], 1);  atomicAdd(&g_deg_in[d.y], 1);
        atomicAdd(&g_deg_in[d.z], 1);  atomicAdd(&g_deg_in[d.w], 1);
    } else {
        for (int e = e4; e < E; e++) {
            atomicAdd(&g_deg_out[src[e]], 1);
            atomicAdd(&g_deg_in[dst[e]], 1);
        }
    }
}

// ---------------- scan ----------------------------------------------------------
__global__ __launch_bounds__(1024) void k_scan1() {
    __shared__ int s[1024];
    int t = threadIdx.x;
    int i = blockIdx.x * 1024 + t;
    int v = (i < NN) ? g_deg_in[i] : 0;
    s[t] = v;
    __syncthreads();
    #pragma unroll
    for (int d = 1; d < 1024; d <<= 1) {
        int x = (t >= d) ? s[t - d] : 0;
        __syncthreads();
        s[t] += x;
        __syncthreads();
    }
    if (i < NN) g_offtmp[i] = s[t];
    if (t == 1023) g_bsum[blockIdx.x] = s[1023];
}

__global__ void k_scan2() {
    __shared__ int s[64];
    int t = threadIdx.x;
    int v = (t < NB) ? g_bsum[t] : 0;
    s[t] = v;
    __syncthreads();
    #pragma unroll
    for (int d = 1; d < 64; d <<= 1) {
        int x = (t >= d) ? s[t - d] : 0;
        __syncthreads();
        s[t] += x;
        __syncthreads();
    }
    if (t < NB) g_bpre[t] = s[t] - v;
}

__global__ __launch_bounds__(1024) void k_scan3() {
    int i = blockIdx.x * 1024 + threadIdx.x;
    if (i >= NN) return;
    int v = g_deg_in[i];
    int excl = g_offtmp[i] - v + g_bpre[blockIdx.x];
    g_off[i] = excl;
    g_ctr[i] = 0;
    if (i == NN - 1) g_off[NN] = excl + v;
    g_norm_dst[i] = rsqrtf(fmaxf((float)v, 1.0f));
    g_norm_src[i] = rsqrtf(fmaxf((float)g_deg_out[i], 1.0f));
}

// ---------------- CSR fill -------------------------------------------------------
__global__ void k_fill(const int* __restrict__ src, const int* __restrict__ dst, int E) {
    int e4 = (blockIdx.x * blockDim.x + threadIdx.x) * 4;
    if (e4 + 3 < E) {
        int4 s = *(const int4*)&src[e4];
        int4 d = *(const int4*)&dst[e4];
        g_csr[g_off[d.x] + atomicAdd(&g_ctr[d.x], 1)] = s.x;
        g_csr[g_off[d.y] + atomicAdd(&g_ctr[d.y], 1)] = s.y;
        g_csr[g_off[d.z] + atomicAdd(&g_ctr[d.z], 1)] = s.z;
        g_csr[g_off[d.w] + atomicAdd(&g_ctr[d.w], 1)] = s.w;
    } else {
        for (int e = e4; e < E; e++) {
            int d = dst[e];
            g_csr[g_off[d] + atomicAdd(&g_ctr[d], 1)] = src[e];
        }
    }
}

// ---------------- GEMM1: g_t = concat(xu,xs) @ W0 (fp16, register-staged A) -----
#define G1_SMEM (2 * 128 * KPAD * 2 + 2 * 64 * KPAD * 2)
__global__ __launch_bounds__(256, 2) void k_gemm1(
    const float* __restrict__ xu, const float* __restrict__ xs) {
    extern __shared__ __align__(16) char sm[];
    __half* Asm = (__half*)sm;
    __half* Bsm = (__half*)(sm + 2 * 128 * KPAD * 2);
    u32 bBase = smem_u32(sm) + 2 * 128 * KPAD * 2;

    int tid = threadIdx.x, warp = tid >> 5, lane = tid & 31;
    int grp = lane >> 2, tig = lane & 3;
    int i0 = blockIdx.x * 128, m0 = warp * 16;

    float4 stage[8];

    auto ldgA = [&](int c) {
        int kb = c * 64;
        #pragma unroll
        for (int q = 0; q < 8; q++) {
            int idx = q * 256 + tid;
            int r = idx >> 4, kq = (idx & 15) << 2;
            int i = i0 + r, k = kb + kq;
            float4 v = make_float4(0.f, 0.f, 0.f, 0.f);
            if (i < NN && k < 2 * NG)
                v = (k < NG) ? *(const float4*)&xu[(size_t)i * NG + k]
                             : *(const float4*)&xs[(size_t)i * NG + (k - NG)];
            stage[q] = v;
        }
    };
    auto stsA = [&](int c) {
        __half* A = Asm + (c & 1) * 128 * KPAD;
        #pragma unroll
        for (int q = 0; q < 8; q++) {
            int idx = q * 256 + tid;
            int r = idx >> 4, kq = (idx & 15) << 2;
            __half2 h0 = __floats2half2_rn(stage[q].x, stage[q].y);
            __half2 h1 = __floats2half2_rn(stage[q].z, stage[q].w);
            *(uint2*)&A[r * KPAD + kq] = make_uint2(*(u32*)&h0, *(u32*)&h1);
        }
    };
    auto ldgB = [&](int c) {
        int kb = c * 64;
        u32 db = bBase + (u32)(c & 1) * (64 * KPAD * 2);
        #pragma unroll
        for (int q = 0; q < 2; q++) {
            int idx = q * 256 + tid;
            int n = idx >> 3, kq = (idx & 7) << 3;
            cp16f(db + (n * KPAD + kq) * 2, g_W0h + n * KW + kb + kq);
        }
        asm volatile("cp.async.commit_group;" ::: "memory");
    };

    float acc[8][4];
    #pragma unroll
    for (int n = 0; n < 8; n++)
        #pragma unroll
        for (int j = 0; j < 4; j++) acc[n][j] = 0.f;

    ldgA(0);
    ldgB(0);
    stsA(0);
    ldgA(1);
    ldgB(1);
    asm volatile("cp.async.wait_group 1;" ::: "memory");
    __syncthreads();

    for (int c = 0; c < 32; c++) {
        const __half* A = Asm + (c & 1) * 128 * KPAD;
        const __half* Bh = Bsm + (c & 1) * 64 * KPAD;

        #pragma unroll
        for (int ks = 0; ks < 4; ks++) {
            int k0 = ks * 16;
            u32 ah0 = *(const u32*)&A[(m0 + grp) * KPAD + k0 + 2 * tig];
            u32 ah1 = *(const u32*)&A[(m0 + grp + 8) * KPAD + k0 + 2 * tig];
            u32 ah2 = *(const u32*)&A[(m0 + grp) * KPAD + k0 + 2 * tig + 8];
            u32 ah3 = *(const u32*)&A[(m0 + grp + 8) * KPAD + k0 + 2 * tig + 8];
            #pragma unroll
            for (int n = 0; n < 8; n++) {
                int nb = n * 8 + grp;
                u32 bh0 = *(const u32*)&Bh[nb * KPAD + k0 + 2 * tig];
                u32 bh1 = *(const u32*)&Bh[nb * KPAD + k0 + 2 * tig + 8];
                mma_f16(acc[n], ah0, ah1, ah2, ah3, bh0, bh1);
            }
        }

        if (c < 31) {
            __syncthreads();
            stsA(c + 1);
            if (c < 30) {
                ldgA(c + 2);
                ldgB(c + 2);
                asm volatile("cp.async.wait_group 1;" ::: "memory");
            } else {
                asm volatile("cp.async.wait_group 0;" ::: "memory");
            }
            __syncthreads();
        }
    }

    int r0 = i0 + m0 + grp;
    int r1 = r0 + 8;
    #pragma unroll
    for (int n = 0; n < 8; n++) {
        int col = n * 8 + tig * 2;
        if (r0 < NN)
            *(__half2*)&g_t[(size_t)r0 * HID + col] = __floats2half2_rn(acc[n][0], acc[n][1]);
        if (r1 < NN)
            *(__half2*)&g_t[(size_t)r1 * HID + col] = __floats2half2_rn(acc[n][2], acc[n][3]);
    }
}

// ---------------- CSR gather: 4 lanes/node, 8 chains/warp, 2 loads per edge ------
// MODE 0: per-edge *norm_src[s]; out(half) = relu(sum*nd + b0)*ns
// MODE 1: plain sum;              out(half) = sum*nd
template <int MODE>
__global__ __launch_bounds__(256) void k_gather(const __half* __restrict__ t,
                                                const float* __restrict__ b0,
                                                __half* __restrict__ optr) {
    int node = (blockIdx.x * 256 + threadIdx.x) >> 2;
    if (node >= NN) return;
    int sub = threadIdx.x & 3;
    const __half* tcol = t + sub * 16;
    int beg = g_off[node], end = g_off[node + 1];

    float acc[16];
    #pragma unroll
    for (int q = 0; q < 16; q++) acc[q] = 0.f;

    int j = beg;
    int sidx[4]; float sns[4];
    bool have = (j + 4 <= end);
    if (have) {
        #pragma unroll
        for (int q = 0; q < 4; q++) sidx[q] = __ldg(&g_csr[j + q]);
        if (MODE == 0) {
            #pragma unroll
            for (int q = 0; q < 4; q++) sns[q] = __ldg(&g_norm_src[sidx[q]]);
        }
    }
    while (have) {
        int jn = j + 4;
        bool haveN = (jn + 4 <= end);
        int nidx[4]; float nns[4];
        if (haveN) {
            #pragma unroll
            for (int q = 0; q < 4; q++) nidx[q] = __ldg(&g_csr[jn + q]);
            if (MODE == 0) {
                #pragma unroll
                for (int q = 0; q < 4; q++) nns[q] = __ldg(&g_norm_src[nidx[q]]);
            }
        }
        // issue all 8 row loads (2 per edge) before accumulation
        uint4 r0v[4], r1v[4];
        #pragma unroll
        for (int q = 0; q < 4; q++) {
            const __half* rp = &tcol[(size_t)sidx[q] * HID];
            r0v[q] = *(const uint4*)rp;
            r1v[q] = *(const uint4*)(rp + 8);
        }
        #pragma unroll
        for (int q = 0; q < 4; q++) {
            float w = (MODE == 0) ? sns[q] : 1.f;
            acc8(acc, r0v[q], w);
            acc8(acc + 8, r1v[q], w);
        }
        j = jn;
        have = haveN;
        #pragma unroll
        for (int q = 0; q < 4; q++) { sidx[q] = nidx[q]; sns[q] = nns[q]; }
    }
    for (; j < end; j++) {
        int s = __ldg(&g_csr[j]);
        const __half* rp = &tcol[(size_t)s * HID];
        uint4 a0 = *(const uint4*)rp;
        uint4 a1 = *(const uint4*)(rp + 8);
        float w = (MODE == 0) ? __ldg(&g_norm_src[s]) : 1.f;
        acc8(acc, a0, w);
        acc8(acc + 8, a1, w);
    }

    float nd = g_norm_dst[node];
    __half2 outv[8];
    if (MODE == 0) {
        float ns = g_norm_src[node];
        float bv[16];
        #pragma unroll
        for (int q4 = 0; q4 < 4; q4++) {
            float4 b = *(const float4*)&b0[sub * 16 + q4 * 4];
            bv[q4 * 4 + 0] = b.x; bv[q4 * 4 + 1] = b.y;
            bv[q4 * 4 + 2] = b.z; bv[q4 * 4 + 3] = b.w;
        }
        #pragma unroll
        for (int q = 0; q < 8; q++) {
            float rx = fmaxf(fmaf(acc[2 * q], nd, bv[2 * q]), 0.f) * ns;
            float ry = fmaxf(fmaf(acc[2 * q + 1], nd, bv[2 * q + 1]), 0.f) * ns;
            outv[q] = __floats2half2_rn(rx, ry);
        }
    } else {
        #pragma unroll
        for (int q = 0; q < 8; q++)
            outv[q] = __floats2half2_rn(acc[2 * q] * nd, acc[2 * q + 1] * nd);
    }
    *(uint4*)&optr[(size_t)node * HID + sub * 16] = ((uint4*)outv)[0];
    *(uint4*)&optr[(size_t)node * HID + sub * 16 + 8] = ((uint4*)outv)[1];
}

// ---------------- fused GEMM2 + epilogue (fp16 z) ---------------------------------
#define KO_SMEM (128 * KPAD * 2 + 2 * 64 * KPAD * 2)
__global__ __launch_bounds__(256, 3) void k_out(
    const float* __restrict__ xu, const float* __restrict__ xs,
    const float* __restrict__ b1, float* __restrict__ out) {
    extern __shared__ __align__(16) char sm[];
    __half* Zs = (__half*)sm;
    __half* Bsm = (__half*)(sm + 128 * KPAD * 2);
    u32 zBase = smem_u32(sm);
    u32 bBase = zBase + 128 * KPAD * 2;

    int tid = threadIdx.x, warp = tid >> 5, lane = tid & 31;
    int grp = lane >> 2, tig = lane & 3;
    int i0 = blockIdx.y * 128;
    int g0 = blockIdx.x * 64;
    int m0 = warp * 16;

    #pragma unroll
    for (int q = 0; q < 4; q++) {
        int idx = q * 256 + tid;
        int r = idx >> 3, kq = (idx & 7) << 3;
        int i = i0 + r;
        const __half* gp = g_z;
        int zf = 0;
        if (i < NN) { gp = g_z + (size_t)i * HID + kq; zf = 16; }
        cp16(zBase + (r * KPAD + kq) * 2, gp, zf);
    }
    #pragma unroll
    for (int q = 0; q < 4; q++) {
        int idx = q * 256 + tid;
        int arr = idx >> 9;
        int rem = idx & 511;
        int n = rem >> 3, kq = (rem & 7) << 3;
        const __half* base = arr ? g_Bg : g_Bb;
        cp16f(bBase + arr * (64 * KPAD * 2) + (n * KPAD + kq) * 2,
              base + (g0 + n) * HID + kq);
    }
    asm volatile("cp.async.commit_group;" ::: "memory");
    asm volatile("cp.async.wait_group 0;" ::: "memory");
    __syncthreads();

    const __half* Bb = Bsm;
    const __half* Bg = Bsm + 64 * KPAD;

    float aB[8][4], aG[8][4];
    #pragma unroll
    for (int n = 0; n < 8; n++)
        #pragma unroll
        for (int j = 0; j < 4; j++) { aB[n][j] = 0.f; aG[n][j] = 0.f; }

    #pragma unroll
    for (int ks = 0; ks < 4; ks++) {
        int k0 = ks * 16;
        u32 ah0 = *(const u32*)&Zs[(m0 + grp) * KPAD + k0 + 2 * tig];
        u32 ah1 = *(const u32*)&Zs[(m0 + grp + 8) * KPAD + k0 + 2 * tig];
        u32 ah2 = *(const u32*)&Zs[(m0 + grp) * KPAD + k0 + 2 * tig + 8];
        u32 ah3 = *(const u32*)&Zs[(m0 + grp + 8) * KPAD + k0 + 2 * tig + 8];
        #pragma unroll
        for (int n = 0; n < 8; n++) {
            int nb = n * 8 + grp;
            u32 b0r = *(const u32*)&Bb[nb * KPAD + k0 + 2 * tig];
            u32 b1r = *(const u32*)&Bb[nb * KPAD + k0 + 2 * tig + 8];
            mma_f16(aB[n], ah0, ah1, ah2, ah3, b0r, b1r);
            u32 g0r = *(const u32*)&Bg[nb * KPAD + k0 + 2 * tig];
            u32 g1r = *(const u32*)&Bg[nb * KPAD + k0 + 2 * tig + 8];
            mma_f16(aG[n], ah0, ah1, ah2, ah3, g0r, g1r);
        }
    }

    int r0 = i0 + m0 + grp;
    int r1 = r0 + 8;
    #pragma unroll
    for (int n = 0; n < 8; n++) {
        int gene = g0 + n * 8 + tig * 2;
        if (gene >= NG) continue;
        float2 bb = *(const float2*)&b1[gene];
        float2 bg = *(const float2*)&b1[NG + gene];
        if (r0 < NN) {
            float2 u = __ldcs((const float2*)&xu[(size_t)r0 * NG + gene]);
            float2 s = __ldcs((const float2*)&xs[(size_t)r0 * NG + gene]);
            float2 o;
            o.x = (aB[n][0] + bb.x) * u.x + (aG[n][0] + bg.x) * s.x;
            o.y = (aB[n][1] + bb.y) * u.y + (aG[n][1] + bg.y) * s.y;
            __stcs((float2*)&out[(size_t)r0 * NG + gene], o);
        }
        if (r1 < NN) {
            float2 u = __ldcs((const float2*)&xu[(size_t)r1 * NG + gene]);
            float2 s = __ldcs((const float2*)&xs[(size_t)r1 * NG + gene]);
            float2 o;
            o.x = (aB[n][2] + bb.x) * u.x + (aG[n][2] + bg.x) * s.x;
            o.y = (aB[n][3] + bb.y) * u.y + (aG[n][3] + bg.y) * s.y;
            __stcs((float2*)&out[(size_t)r1 * NG + gene], o);
        }
    }
}

// ---------------- host launcher ---------------------------------------------------
extern "C" void kernel_launch(void* const* d_in, const int* in_sizes, int n_in,
                              void* d_out, int out_size) {
    const float* xu = (const float*)d_in[0];
    const float* xs = (const float*)d_in[1];
    const float* W0 = (const float*)d_in[2];
    const float* b0 = (const float*)d_in[3];
    const float* W1 = (const float*)d_in[4];
    const float* b1 = (const float*)d_in[5];
    const int* src = (const int*)d_in[6];
    const int* dst = (const int*)d_in[7];
    int E = in_sizes[6];
    float* out = (float*)d_out;

    void *p_degi, *p_dego, *p_t, *p_hs, *p_z;
    cudaGetSymbolAddress(&p_degi, g_deg_in);
    cudaGetSymbolAddress(&p_dego, g_deg_out);
    cudaGetSymbolAddress(&p_t, g_t);
    cudaGetSymbolAddress(&p_hs, g_hs);
    cudaGetSymbolAddress(&p_z, g_z);

    static cudaStream_t s1 = nullptr;
    static cudaEvent_t evFork = nullptr, evB = nullptr;
    static int attr_done = 0;
    if (!attr_done) {
        cudaFuncSetAttribute(k_gemm1, cudaFuncAttributeMaxDynamicSharedMemorySize, G1_SMEM);
        cudaFuncSetAttribute(k_out, cudaFuncAttributeMaxDynamicSharedMemorySize, KO_SMEM);
        cudaStreamCreateWithFlags(&s1, cudaStreamNonBlocking);
        cudaEventCreateWithFlags(&evFork, cudaEventDisableTiming);
        cudaEventCreateWithFlags(&evB, cudaEventDisableTiming);
        attr_done = 1;
    }

    cudaEventRecord(evFork, 0);
    cudaStreamWaitEvent(s1, evFork, 0);

    // chain B: CSR build (on s1)
    cudaMemsetAsync(p_degi, 0, NN * sizeof(int), s1);
    cudaMemsetAsync(p_dego, 0, NN * sizeof(int), s1);
    k_count<<<(E / 4 + 255) / 256, 256, 0, s1>>>(src, dst, E);
    k_scan1<<<NB, 1024, 0, s1>>>();
    k_scan2<<<1, 64, 0, s1>>>();
    k_scan3<<<NB, 1024, 0, s1>>>();
    k_fill<<<(E / 4 + 255) / 256, 256, 0, s1>>>(src, dst, E);
    cudaEventRecord(evB, s1);

    // chain A: weights + GEMM1 (on stream 0)
    k_prep<<<(HID * KW + 255) / 256, 256>>>(W0, W1);
    k_gemm1<<<(NN + 127) / 128, 256, G1_SMEM>>>(xu, xs);

    cudaStreamWaitEvent(0, evB, 0);

    k_gather<0><<<(NN * 4 + 255) / 256, 256>>>((const __half*)p_t, b0, (__half*)p_hs);
    k_gather<1><<<(NN * 4 + 255) / 256, 256>>>((const __half*)p_hs, b0, (__half*)p_z);
    k_out<<<dim3(16, (NN + 127) / 128), 256, KO_SMEM>>>(xu, xs, b1, out);
}

// round 17
// speedup vs baseline: 1.2517x; 1.2517x over previous
#include <cuda_runtime.h>
#include <cuda_bf16.h>
#include <cuda_fp16.h>

#define NN 50000
#define NG 1000
#define HID 64
#define NE_MAX 1600000
#define KW 2048
#define KPAD 72
#define NB 49

typedef unsigned long long u64;
typedef unsigned int u32;

// ---------------- scratch ----------------------------------------------------
__device__ __half g_t[NN * HID];
__device__ __half g_hs[NN * HID];
__device__ __half g_z[NN * HID];
__device__ int g_deg_in[NN];
__device__ int g_deg_out[NN];
__device__ int g_off[NN + 1];
__device__ int g_offtmp[NN];
__device__ int g_ctr[NN];
__device__ int g_bsum[NB];
__device__ int g_bpre[NB];
__device__ int g_csr[NE_MAX];
__device__ float g_norm_src[NN];
__device__ float g_norm_dst[NN];
__device__ __half g_W0h[HID * KW];
__device__ __half g_Bb[1024 * HID];
__device__ __half g_Bg[1024 * HID];

// ---------------- helpers -----------------------------------------------------
__device__ __forceinline__ u32 smem_u32(const void* p) {
    u32 a;
    asm("{ .reg .u64 t; cvta.to.shared.u64 t, %1; cvt.u32.u64 %0, t; }" : "=r"(a) : "l"(p));
    return a;
}
__device__ __forceinline__ void mma_f16(float* d, u32 a0, u32 a1, u32 a2, u32 a3,
                                        u32 b0, u32 b1) {
    asm volatile(
        "mma.sync.aligned.m16n8k16.row.col.f32.f16.f16.f32 "
        "{%0,%1,%2,%3}, {%4,%5,%6,%7}, {%8,%9}, {%0,%1,%2,%3};"
        : "+f"(d[0]), "+f"(d[1]), "+f"(d[2]), "+f"(d[3])
        : "r"(a0), "r"(a1), "r"(a2), "r"(a3), "r"(b0), "r"(b1));
}
__device__ __forceinline__ void cp16(u32 daddr, const void* gp, int zf) {
    asm volatile("cp.async.ca.shared.global [%0], [%1], 16, %2;"
                 :: "r"(daddr), "l"(gp), "r"(zf));
}
__device__ __forceinline__ void cp16f(u32 daddr, const void* gp) {
    asm volatile("cp.async.ca.shared.global [%0], [%1], 16;"
                 :: "r"(daddr), "l"(gp));
}
__device__ __forceinline__ void acc8(float* acc, uint4 raw, float w) {
    float2 p0 = __half22float2(*(__half2*)&raw.x);
    float2 p1 = __half22float2(*(__half2*)&raw.y);
    float2 p2 = __half22float2(*(__half2*)&raw.z);
    float2 p3 = __half22float2(*(__half2*)&raw.w);
    acc[0] = fmaf(p0.x, w, acc[0]); acc[1] = fmaf(p0.y, w, acc[1]);
    acc[2] = fmaf(p1.x, w, acc[2]); acc[3] = fmaf(p1.y, w, acc[3]);
    acc[4] = fmaf(p2.x, w, acc[4]); acc[5] = fmaf(p2.y, w, acc[5]);
    acc[6] = fmaf(p3.x, w, acc[6]); acc[7] = fmaf(p3.y, w, acc[7]);
}

// ---------------- weight pre-conversion ---------------------------------------
__global__ void k_prep(const float* __restrict__ W0, const float* __restrict__ W1) {
    int idx = blockIdx.x * blockDim.x + threadIdx.x;
    if (idx < HID * KW) {
        int n = idx / KW, k = idx % KW;
        float w = (k < 2 * NG) ? W0[k * HID + n] : 0.f;
        g_W0h[idx] = __float2half(w);
    }
    if (idx < 1024 * HID) {
        int g = idx / HID, k = idx % HID;
        float wb = (g < NG) ? W1[k * 2 * NG + g] : 0.f;
        float wg = (g < NG) ? W1[k * 2 * NG + NG + g] : 0.f;
        g_Bb[idx] = __float2half(wb);
        g_Bg[idx] = __float2half(wg);
    }
}

// ---------------- degree count -------------------------------------------------
__global__ void k_count(const int* __restrict__ src, const int* __restrict__ dst, int E) {
    int e4 = (blockIdx.x * blockDim.x + threadIdx.x) * 4;
    if (e4 + 3 < E) {
        int4 s = *(const int4*)&src[e4];
        int4 d = *(const int4*)&dst[e4];
        atomicAdd(&g_deg_out[s.x], 1); atomicAdd(&g_deg_out[s.y], 1);
        atomicAdd(&g_deg_out[s.z], 1); atomicAdd(&g_deg_out[s.w], 1);
        atomicAdd(&g_deg_in[d.x], 1);  atomicAdd(&g_deg_in[d.y], 1);
        atomicAdd(&g_deg_in[d.z], 1);  atomicAdd(&g_deg_in[d.w], 1);
    } else {
        for (int e = e4; e < E; e++) {
            atomicAdd(&g_deg_out[src[e]], 1);
            atomicAdd(&g_deg_in[dst[e]], 1);
        }
    }
}

// ---------------- scan ----------------------------------------------------------
__global__ __launch_bounds__(1024) void k_scan1() {
    __shared__ int s[1024];
    int t = threadIdx.x;
    int i = blockIdx.x * 1024 + t;
    int v = (i < NN) ? g_deg_in[i] : 0;
    s[t] = v;
    __syncthreads();
    #pragma unroll
    for (int d = 1; d < 1024; d <<= 1) {
        int x = (t >= d) ? s[t - d] : 0;
        __syncthreads();
        s[t] += x;
        __syncthreads();
    }
    if (i < NN) g_offtmp[i] = s[t];
    if (t == 1023) g_bsum[blockIdx.x] = s[1023];
}

__global__ void k_scan2() {
    __shared__ int s[64];
    int t = threadIdx.x;
    int v = (t < NB) ? g_bsum[t] : 0;
    s[t] = v;
    __syncthreads();
    #pragma unroll
    for (int d = 1; d < 64; d <<= 1) {
        int x = (t >= d) ? s[t - d] : 0;
        __syncthreads();
        s[t] += x;
        __syncthreads();
    }
    if (t < NB) g_bpre[t] = s[t] - v;
}

__global__ __launch_bounds__(1024) void k_scan3() {
    int i = blockIdx.x * 1024 + threadIdx.x;
    if (i >= NN) return;
    int v = g_deg_in[i];
    int excl = g_offtmp[i] - v + g_bpre[blockIdx.x];
    g_off[i] = excl;
    g_ctr[i] = 0;
    if (i == NN - 1) g_off[NN] = excl + v;
    g_norm_dst[i] = rsqrtf(fmaxf((float)v, 1.0f));
    g_norm_src[i] = rsqrtf(fmaxf((float)g_deg_out[i], 1.0f));
}

// ---------------- CSR fill -------------------------------------------------------
__global__ void k_fill(const int* __restrict__ src, const int* __restrict__ dst, int E) {
    int e4 = (blockIdx.x * blockDim.x + threadIdx.x) * 4;
    if (e4 + 3 < E) {
        int4 s = *(const int4*)&src[e4];
        int4 d = *(const int4*)&dst[e4];
        g_csr[g_off[d.x] + atomicAdd(&g_ctr[d.x], 1)] = s.x;
        g_csr[g_off[d.y] + atomicAdd(&g_ctr[d.y], 1)] = s.y;
        g_csr[g_off[d.z] + atomicAdd(&g_ctr[d.z], 1)] = s.z;
        g_csr[g_off[d.w] + atomicAdd(&g_ctr[d.w], 1)] = s.w;
    } else {
        for (int e = e4; e < E; e++) {
            int d = dst[e];
            g_csr[g_off[d] + atomicAdd(&g_ctr[d], 1)] = src[e];
        }
    }
}

// ---------------- GEMM1: g_t = concat(xu,xs) @ W0 (fp16, register-staged A) -----
#define G1_SMEM (2 * 128 * KPAD * 2 + 2 * 64 * KPAD * 2)
__global__ __launch_bounds__(256, 2) void k_gemm1(
    const float* __restrict__ xu, const float* __restrict__ xs) {
    extern __shared__ __align__(16) char sm[];
    __half* Asm = (__half*)sm;
    __half* Bsm = (__half*)(sm + 2 * 128 * KPAD * 2);
    u32 bBase = smem_u32(sm) + 2 * 128 * KPAD * 2;

    int tid = threadIdx.x, warp = tid >> 5, lane = tid & 31;
    int grp = lane >> 2, tig = lane & 3;
    int i0 = blockIdx.x * 128, m0 = warp * 16;

    float4 stage[8];

    auto ldgA = [&](int c) {
        int kb = c * 64;
        #pragma unroll
        for (int q = 0; q < 8; q++) {
            int idx = q * 256 + tid;
            int r = idx >> 4, kq = (idx & 15) << 2;
            int i = i0 + r, k = kb + kq;
            float4 v = make_float4(0.f, 0.f, 0.f, 0.f);
            if (i < NN && k < 2 * NG)
                v = (k < NG) ? *(const float4*)&xu[(size_t)i * NG + k]
                             : *(const float4*)&xs[(size_t)i * NG + (k - NG)];
            stage[q] = v;
        }
    };
    auto stsA = [&](int c) {
        __half* A = Asm + (c & 1) * 128 * KPAD;
        #pragma unroll
        for (int q = 0; q < 8; q++) {
            int idx = q * 256 + tid;
            int r = idx >> 4, kq = (idx & 15) << 2;
            __half2 h0 = __floats2half2_rn(stage[q].x, stage[q].y);
            __half2 h1 = __floats2half2_rn(stage[q].z, stage[q].w);
            *(uint2*)&A[r * KPAD + kq] = make_uint2(*(u32*)&h0, *(u32*)&h1);
        }
    };
    auto ldgB = [&](int c) {
        int kb = c * 64;
        u32 db = bBase + (u32)(c & 1) * (64 * KPAD * 2);
        #pragma unroll
        for (int q = 0; q < 2; q++) {
            int idx = q * 256 + tid;
            int n = idx >> 3, kq = (idx & 7) << 3;
            cp16f(db + (n * KPAD + kq) * 2, g_W0h + n * KW + kb + kq);
        }
        asm volatile("cp.async.commit_group;" ::: "memory");
    };

    float acc[8][4];
    #pragma unroll
    for (int n = 0; n < 8; n++)
        #pragma unroll
        for (int j = 0; j < 4; j++) acc[n][j] = 0.f;

    ldgA(0);
    ldgB(0);
    stsA(0);
    ldgA(1);
    ldgB(1);
    asm volatile("cp.async.wait_group 1;" ::: "memory");
    __syncthreads();

    for (int c = 0; c < 32; c++) {
        const __half* A = Asm + (c & 1) * 128 * KPAD;
        const __half* Bh = Bsm + (c & 1) * 64 * KPAD;

        #pragma unroll
        for (int ks = 0; ks < 4; ks++) {
            int k0 = ks * 16;
            u32 ah0 = *(const u32*)&A[(m0 + grp) * KPAD + k0 + 2 * tig];
            u32 ah1 = *(const u32*)&A[(m0 + grp + 8) * KPAD + k0 + 2 * tig];
            u32 ah2 = *(const u32*)&A[(m0 + grp) * KPAD + k0 + 2 * tig + 8];
            u32 ah3 = *(const u32*)&A[(m0 + grp + 8) * KPAD + k0 + 2 * tig + 8];
            #pragma unroll
            for (int n = 0; n < 8; n++) {
                int nb = n * 8 + grp;
                u32 bh0 = *(const u32*)&Bh[nb * KPAD + k0 + 2 * tig];
                u32 bh1 = *(const u32*)&Bh[nb * KPAD + k0 + 2 * tig + 8];
                mma_f16(acc[n], ah0, ah1, ah2, ah3, bh0, bh1);
            }
        }

        if (c < 31) {
            __syncthreads();
            stsA(c + 1);
            if (c < 30) {
                ldgA(c + 2);
                ldgB(c + 2);
                asm volatile("cp.async.wait_group 1;" ::: "memory");
            } else {
                asm volatile("cp.async.wait_group 0;" ::: "memory");
            }
            __syncthreads();
        }
    }

    int r0 = i0 + m0 + grp;
    int r1 = r0 + 8;
    #pragma unroll
    for (int n = 0; n < 8; n++) {
        int col = n * 8 + tig * 2;
        if (r0 < NN)
            *(__half2*)&g_t[(size_t)r0 * HID + col] = __floats2half2_rn(acc[n][0], acc[n][1]);
        if (r1 < NN)
            *(__half2*)&g_t[(size_t)r1 * HID + col] = __floats2half2_rn(acc[n][2], acc[n][3]);
    }
}

// ---------------- CSR gather: 8 lanes per node, 4 chains/warp --------------------
template <int MODE>
__global__ __launch_bounds__(256) void k_gather(const __half* __restrict__ t,
                                                const float* __restrict__ b0,
                                                __half* __restrict__ optr) {
    int node = (blockIdx.x * 256 + threadIdx.x) >> 3;
    if (node >= NN) return;
    int sub = threadIdx.x & 7;
    const __half* tcol = t + sub * 8;
    int beg = g_off[node], end = g_off[node + 1];

    float acc[8];
    #pragma unroll
    for (int q = 0; q < 8; q++) acc[q] = 0.f;

    int j = beg;
    int sidx[8]; float sns[8];
    bool have = (j + 8 <= end);
    if (have) {
        #pragma unroll
        for (int q = 0; q < 8; q++) sidx[q] = __ldg(&g_csr[j + q]);
        if (MODE == 0) {
            #pragma unroll
            for (int q = 0; q < 8; q++) sns[q] = __ldg(&g_norm_src[sidx[q]]);
        }
    }
    while (have) {
        int jn = j + 8;
        bool haveN = (jn + 8 <= end);
        int nidx[8]; float nns[8];
        if (haveN) {
            #pragma unroll
            for (int q = 0; q < 8; q++) nidx[q] = __ldg(&g_csr[jn + q]);
            if (MODE == 0) {
                #pragma unroll
                for (int q = 0; q < 8; q++) nns[q] = __ldg(&g_norm_src[nidx[q]]);
            }
        }
        #pragma unroll
        for (int q = 0; q < 8; q++) {
            uint4 raw = *(const uint4*)&tcol[(size_t)sidx[q] * HID];
            acc8(acc, raw, (MODE == 0) ? sns[q] : 1.f);
        }
        j = jn;
        have = haveN;
        #pragma unroll
        for (int q = 0; q < 8; q++) { sidx[q] = nidx[q]; sns[q] = nns[q]; }
    }
    for (; j < end; j++) {
        int s = __ldg(&g_csr[j]);
        uint4 raw = *(const uint4*)&tcol[(size_t)s * HID];
        float w = (MODE == 0) ? __ldg(&g_norm_src[s]) : 1.f;
        acc8(acc, raw, w);
    }

    float nd = g_norm_dst[node];
    __half2 outv[4];
    if (MODE == 0) {
        float ns = g_norm_src[node];
        float4 ba = *(const float4*)&b0[sub * 8];
        float4 bc = *(const float4*)&b0[sub * 8 + 4];
        float bv[8] = {ba.x, ba.y, ba.z, ba.w, bc.x, bc.y, bc.z, bc.w};
        #pragma unroll
        for (int q = 0; q < 4; q++) {
            float rx = fmaxf(fmaf(acc[2 * q], nd, bv[2 * q]), 0.f) * ns;
            float ry = fmaxf(fmaf(acc[2 * q + 1], nd, bv[2 * q + 1]), 0.f) * ns;
            outv[q] = __floats2half2_rn(rx, ry);
        }
    } else {
        #pragma unroll
        for (int q = 0; q < 4; q++)
            outv[q] = __floats2half2_rn(acc[2 * q] * nd, acc[2 * q + 1] * nd);
    }
    *(uint4*)&optr[(size_t)node * HID + sub * 8] = *(uint4*)outv;
}

// ---------------- fused GEMM2 + epilogue (fp16 z) ---------------------------------
#define KO_SMEM (128 * KPAD * 2 + 2 * 64 * KPAD * 2)
__global__ __launch_bounds__(256, 3) void k_out(
    const float* __restrict__ xu, const float* __restrict__ xs,
    const float* __restrict__ b1, float* __restrict__ out) {
    extern __shared__ __align__(16) char sm[];
    __half* Zs = (__half*)sm;
    __half* Bsm = (__half*)(sm + 128 * KPAD * 2);
    u32 zBase = smem_u32(sm);
    u32 bBase = zBase + 128 * KPAD * 2;

    int tid = threadIdx.x, warp = tid >> 5, lane = tid & 31;
    int grp = lane >> 2, tig = lane & 3;
    int i0 = blockIdx.y * 128;
    int g0 = blockIdx.x * 64;
    int m0 = warp * 16;

    #pragma unroll
    for (int q = 0; q < 4; q++) {
        int idx = q * 256 + tid;
        int r = idx >> 3, kq = (idx & 7) << 3;
        int i = i0 + r;
        const __half* gp = g_z;
        int zf = 0;
        if (i < NN) { gp = g_z + (size_t)i * HID + kq; zf = 16; }
        cp16(zBase + (r * KPAD + kq) * 2, gp, zf);
    }
    #pragma unroll
    for (int q = 0; q < 4; q++) {
        int idx = q * 256 + tid;
        int arr = idx >> 9;
        int rem = idx & 511;
        int n = rem >> 3, kq = (rem & 7) << 3;
        const __half* base = arr ? g_Bg : g_Bb;
        cp16f(bBase + arr * (64 * KPAD * 2) + (n * KPAD + kq) * 2,
              base + (g0 + n) * HID + kq);
    }
    asm volatile("cp.async.commit_group;" ::: "memory");
    asm volatile("cp.async.wait_group 0;" ::: "memory");
    __syncthreads();

    const __half* Bb = Bsm;
    const __half* Bg = Bsm + 64 * KPAD;

    float aB[8][4], aG[8][4];
    #pragma unroll
    for (int n = 0; n < 8; n++)
        #pragma unroll
        for (int j = 0; j < 4; j++) { aB[n][j] = 0.f; aG[n][j] = 0.f; }

    #pragma unroll
    for (int ks = 0; ks < 4; ks++) {
        int k0 = ks * 16;
        u32 ah0 = *(const u32*)&Zs[(m0 + grp) * KPAD + k0 + 2 * tig];
        u32 ah1 = *(const u32*)&Zs[(m0 + grp + 8) * KPAD + k0 + 2 * tig];
        u32 ah2 = *(const u32*)&Zs[(m0 + grp) * KPAD + k0 + 2 * tig + 8];
        u32 ah3 = *(const u32*)&Zs[(m0 + grp + 8) * KPAD + k0 + 2 * tig + 8];
        #pragma unroll
        for (int n = 0; n < 8; n++) {
            int nb = n * 8 + grp;
            u32 b0r = *(const u32*)&Bb[nb * KPAD + k0 + 2 * tig];
            u32 b1r = *(const u32*)&Bb[nb * KPAD + k0 + 2 * tig + 8];
            mma_f16(aB[n], ah0, ah1, ah2, ah3, b0r, b1r);
            u32 g0r = *(const u32*)&Bg[nb * KPAD + k0 + 2 * tig];
            u32 g1r = *(const u32*)&Bg[nb * KPAD + k0 + 2 * tig + 8];
            mma_f16(aG[n], ah0, ah1, ah2, ah3, g0r, g1r);
        }
    }

    int r0 = i0 + m0 + grp;
    int r1 = r0 + 8;
    #pragma unroll
    for (int n = 0; n < 8; n++) {
        int gene = g0 + n * 8 + tig * 2;
        if (gene >= NG) continue;
        float2 bb = *(const float2*)&b1[gene];
        float2 bg = *(const float2*)&b1[NG + gene];
        if (r0 < NN) {
            float2 u = *(const float2*)&xu[(size_t)r0 * NG + gene];
            float2 s = *(const float2*)&xs[(size_t)r0 * NG + gene];
            float2 o;
            o.x = (aB[n][0] + bb.x) * u.x + (aG[n][0] + bg.x) * s.x;
            o.y = (aB[n][1] + bb.y) * u.y + (aG[n][1] + bg.y) * s.y;
            __stcs((float2*)&out[(size_t)r0 * NG + gene], o);
        }
        if (r1 < NN) {
            float2 u = *(const float2*)&xu[(size_t)r1 * NG + gene];
            float2 s = *(const float2*)&xs[(size_t)r1 * NG + gene];
            float2 o;
            o.x = (aB[n][2] + bb.x) * u.x + (aG[n][2] + bg.x) * s.x;
            o.y = (aB[n][3] + bb.y) * u.y + (aG[n][3] + bg.y) * s.y;
            __stcs((float2*)&out[(size_t)r1 * NG + gene], o);
        }
    }
}

// ---------------- host launcher ---------------------------------------------------
extern "C" void kernel_launch(void* const* d_in, const int* in_sizes, int n_in,
                              void* d_out, int out_size) {
    const float* xu = (const float*)d_in[0];
    const float* xs = (const float*)d_in[1];
    const float* W0 = (const float*)d_in[2];
    const float* b0 = (const float*)d_in[3];
    const float* W1 = (const float*)d_in[4];
    const float* b1 = (const float*)d_in[5];
    const int* src = (const int*)d_in[6];
    const int* dst = (const int*)d_in[7];
    int E = in_sizes[6];
    float* out = (float*)d_out;

    void *p_degi, *p_dego, *p_t, *p_hs, *p_z;
    cudaGetSymbolAddress(&p_degi, g_deg_in);
    cudaGetSymbolAddress(&p_dego, g_deg_out);
    cudaGetSymbolAddress(&p_t, g_t);
    cudaGetSymbolAddress(&p_hs, g_hs);
    cudaGetSymbolAddress(&p_z, g_z);

    static cudaStream_t s1 = nullptr;
    static cudaEvent_t evFork = nullptr, evB = nullptr;
    static int attr_done = 0;
    if (!attr_done) {
        cudaFuncSetAttribute(k_gemm1, cudaFuncAttributeMaxDynamicSharedMemorySize, G1_SMEM);
        cudaFuncSetAttribute(k_out, cudaFuncAttributeMaxDynamicSharedMemorySize, KO_SMEM);
        cudaStreamCreateWithFlags(&s1, cudaStreamNonBlocking);
        cudaEventCreateWithFlags(&evFork, cudaEventDisableTiming);
        cudaEventCreateWithFlags(&evB, cudaEventDisableTiming);
        attr_done = 1;
    }

    cudaEventRecord(evFork, 0);
    cudaStreamWaitEvent(s1, evFork, 0);

    // chain B: CSR build (on s1)
    cudaMemsetAsync(p_degi, 0, NN * sizeof(int), s1);
    cudaMemsetAsync(p_dego, 0, NN * sizeof(int), s1);
    k_count<<<(E / 4 + 255) / 256, 256, 0, s1>>>(src, dst, E);
    k_scan1<<<NB, 1024, 0, s1>>>();
    k_scan2<<<1, 64, 0, s1>>>();
    k_scan3<<<NB, 1024, 0, s1>>>();
    k_fill<<<(E / 4 + 255) / 256, 256, 0, s1>>>(src, dst, E);
    cudaEventRecord(evB, s1);

    // chain A: weights + GEMM1 (on stream 0)
    k_prep<<<(HID * KW + 255) / 256, 256>>>(W0, W1);
    k_gemm1<<<(NN + 127) / 128, 256, G1_SMEM>>>(xu, xs);

    cudaStreamWaitEvent(0, evB, 0);

    k_gather<0><<<(NN * 8 + 255) / 256, 256>>>((const __half*)p_t, b0, (__half*)p_hs);
    k_gather<1><<<(NN * 8 + 255) / 256, 256>>>((const __half*)p_hs, b0, (__half*)p_z);
    k_out<<<dim3(16, (NN + 127) / 128), 256, KO_SMEM>>>(xu, xs, b1, out);
}